// round 3
// baseline (speedup 1.0000x reference)
#include <cuda_runtime.h>
#include <cstdint>

#define N_NODES 100000
#define N_EDGES 3200000

// Scratch (device globals — no allocation allowed)
__device__ float  g_deg[N_NODES];
__device__ float  g_dinv[N_NODES];
__device__ float2 g_agg1[N_NODES];   // aggregated input features (A_hat X)
__device__ float2 g_p[N_NODES];      // h1 @ W2 (pre-aggregation layer-2 messages)
__device__ float2 g_agg2[N_NODES];   // aggregated layer-2

// ---------------------------------------------------------------------------
__global__ void k_init_deg() {
    int i = blockIdx.x * blockDim.x + threadIdx.x;
    if (i < N_NODES) g_deg[i] = 1.0f;   // self-loop
}

__global__ void k_degree(const int* __restrict__ dst) {
    int e = blockIdx.x * blockDim.x + threadIdx.x;
    if (e < N_EDGES) {
        atomicAdd(&g_deg[dst[e]], 1.0f);
    }
}

__global__ void k_dinv_seed(const float2* __restrict__ x2) {
    int i = blockIdx.x * blockDim.x + threadIdx.x;
    if (i < N_NODES) {
        float di = rsqrtf(g_deg[i]);    // deg >= 1 always
        g_dinv[i] = di;
        float2 xi = x2[i];
        float s = di * di;              // self-loop norm
        g_agg1[i] = make_float2(xi.x * s, xi.y * s);
    }
}

__global__ void k_scatter1(const int* __restrict__ src,
                           const int* __restrict__ dst,
                           const float2* __restrict__ x2) {
    int e = blockIdx.x * blockDim.x + threadIdx.x;
    if (e < N_EDGES) {
        int s = src[e];
        int d = dst[e];
        float n = g_dinv[s] * g_dinv[d];
        float2 v = x2[s];
        atomicAdd(&g_agg1[d].x, v.x * n);
        atomicAdd(&g_agg1[d].y, v.y * n);
    }
}

__global__ void k_mid(const float* __restrict__ W1,   // [2,16] row-major
                      const float* __restrict__ b1,   // [16]
                      const float* __restrict__ W2) { // [16,2] row-major
    int i = blockIdx.x * blockDim.x + threadIdx.x;
    if (i >= N_NODES) return;
    float2 a = g_agg1[i];
    float px = 0.0f, py = 0.0f;
#pragma unroll
    for (int j = 0; j < 16; j++) {
        float h = a.x * __ldg(&W1[j]) + a.y * __ldg(&W1[16 + j]) + __ldg(&b1[j]);
        h = fmaxf(h, 0.0f);             // relu
        px += h * __ldg(&W2[2 * j]);
        py += h * __ldg(&W2[2 * j + 1]);
    }
    g_p[i] = make_float2(px, py);
    float di = g_dinv[i];
    float s = di * di;                  // self-loop norm
    g_agg2[i] = make_float2(px * s, py * s);
}

__global__ void k_scatter2(const int* __restrict__ src,
                           const int* __restrict__ dst) {
    int e = blockIdx.x * blockDim.x + threadIdx.x;
    if (e < N_EDGES) {
        int s = src[e];
        int d = dst[e];
        float n = g_dinv[s] * g_dinv[d];
        float2 v = g_p[s];
        atomicAdd(&g_agg2[d].x, v.x * n);
        atomicAdd(&g_agg2[d].y, v.y * n);
    }
}

__global__ void k_out(const float* __restrict__ b2, float2* __restrict__ out) {
    int i = blockIdx.x * blockDim.x + threadIdx.x;
    if (i >= N_NODES) return;
    float2 z = g_agg2[i];
    z.x += __ldg(&b2[0]);
    z.y += __ldg(&b2[1]);
    float m = fmaxf(z.x, z.y);
    float lse = m + logf(expf(z.x - m) + expf(z.y - m));
    out[i] = make_float2(z.x - lse, z.y - lse);
}

// ---------------------------------------------------------------------------
extern "C" void kernel_launch(void* const* d_in, const int* in_sizes, int n_in,
                              void* d_out, int out_size) {
    const float* x  = (const float*)d_in[0];   // [N,2]
    const int*   ei = (const int*)d_in[1];     // [2,E] int32 (JAX x64 disabled)
    const float* W1 = (const float*)d_in[2];   // [2,16]
    const float* b1 = (const float*)d_in[3];   // [16]
    const float* W2 = (const float*)d_in[4];   // [16,2]
    const float* b2 = (const float*)d_in[5];   // [2]
    float2* out = (float2*)d_out;

    const int* src = ei;
    const int* dst = ei + N_EDGES;
    const float2* x2 = (const float2*)x;

    const int T = 256;
    const int gN = (N_NODES + T - 1) / T;
    const int gE = (N_EDGES + T - 1) / T;

    k_init_deg<<<gN, T>>>();
    k_degree<<<gE, T>>>(dst);
    k_dinv_seed<<<gN, T>>>(x2);
    k_scatter1<<<gE, T>>>(src, dst, x2);
    k_mid<<<gN, T>>>(W1, b1, W2);
    k_scatter2<<<gE, T>>>(src, dst);
    k_out<<<gN, T>>>(b2, out);
}

// round 4
// speedup vs baseline: 1.6788x; 1.6788x over previous
#include <cuda_runtime.h>
#include <cstdint>

#define N_NODES 100000
#define N_EDGES 3200000

// Scratch (device globals — no allocation allowed)
__device__ float  g_deg[N_NODES];
__device__ float  g_dinv[N_NODES];
__device__ float2 g_xs[N_NODES];     // x[i] * dinv[i]  (premultiplied layer-1 msg)
__device__ float2 g_agg1[N_NODES];   // Σ_src xs[src]  (+ self term xs[i])
__device__ float2 g_ps[N_NODES];     // (h1@W2)[i] * dinv[i] (premultiplied layer-2 msg)
__device__ float2 g_agg2[N_NODES];   // Σ_src ps[src]  (+ self term ps[i])

__device__ __forceinline__ void red_add_f2(float2* addr, float2 v) {
    asm volatile("red.global.add.v2.f32 [%0], {%1, %2};"
                 :: "l"(addr), "f"(v.x), "f"(v.y) : "memory");
}

// ---------------------------------------------------------------------------
__global__ void k_init_deg() {
    int i = blockIdx.x * blockDim.x + threadIdx.x;
    if (i < N_NODES) g_deg[i] = 1.0f;   // self-loop
}

__global__ void k_degree(const int* __restrict__ dst) {
    int e = blockIdx.x * blockDim.x + threadIdx.x;
    if (e < N_EDGES) {
        atomicAdd(&g_deg[dst[e]], 1.0f);
    }
}

// dinv, premultiplied features, and agg1 seeded with the self-loop term xs[i]
__global__ void k_pre1(const float2* __restrict__ x2) {
    int i = blockIdx.x * blockDim.x + threadIdx.x;
    if (i < N_NODES) {
        float di = rsqrtf(g_deg[i]);    // deg >= 1 always
        g_dinv[i] = di;
        float2 xi = x2[i];
        float2 xs = make_float2(xi.x * di, xi.y * di);
        g_xs[i] = xs;
        g_agg1[i] = xs;                 // self-loop contributes dinv[i]*xs[i]; dinv applied in k_mid
    }
}

// Pure gather+scatter: no norm math in the edge loop.
__global__ void k_scatter1(const int* __restrict__ src,
                           const int* __restrict__ dst) {
    int e = blockIdx.x * blockDim.x + threadIdx.x;
    if (e < N_EDGES) {
        int s = src[e];
        int d = dst[e];
        red_add_f2(&g_agg1[d], g_xs[s]);
    }
}

__global__ void k_mid(const float* __restrict__ W1,   // [2,16] row-major
                      const float* __restrict__ b1,   // [16]
                      const float* __restrict__ W2) { // [16,2] row-major
    int i = blockIdx.x * blockDim.x + threadIdx.x;
    if (i >= N_NODES) return;
    float di = g_dinv[i];
    float2 t = g_agg1[i];
    float2 a = make_float2(t.x * di, t.y * di);       // finish layer-1 normalization
    float px = 0.0f, py = 0.0f;
#pragma unroll
    for (int j = 0; j < 16; j++) {
        float h = a.x * __ldg(&W1[j]) + a.y * __ldg(&W1[16 + j]) + __ldg(&b1[j]);
        h = fmaxf(h, 0.0f);             // relu
        px += h * __ldg(&W2[2 * j]);
        py += h * __ldg(&W2[2 * j + 1]);
    }
    float2 ps = make_float2(px * di, py * di);        // premultiply layer-2 msg
    g_ps[i] = ps;
    g_agg2[i] = ps;                                   // self-loop seed
}

__global__ void k_scatter2(const int* __restrict__ src,
                           const int* __restrict__ dst) {
    int e = blockIdx.x * blockDim.x + threadIdx.x;
    if (e < N_EDGES) {
        int s = src[e];
        int d = dst[e];
        red_add_f2(&g_agg2[d], g_ps[s]);
    }
}

__global__ void k_out(const float* __restrict__ b2, float2* __restrict__ out) {
    int i = blockIdx.x * blockDim.x + threadIdx.x;
    if (i >= N_NODES) return;
    float di = g_dinv[i];
    float2 t = g_agg2[i];
    float2 z = make_float2(t.x * di + __ldg(&b2[0]),
                           t.y * di + __ldg(&b2[1]));
    float m = fmaxf(z.x, z.y);
    float lse = m + logf(expf(z.x - m) + expf(z.y - m));
    out[i] = make_float2(z.x - lse, z.y - lse);
}

// ---------------------------------------------------------------------------
extern "C" void kernel_launch(void* const* d_in, const int* in_sizes, int n_in,
                              void* d_out, int out_size) {
    const float* x  = (const float*)d_in[0];   // [N,2]
    const int*   ei = (const int*)d_in[1];     // [2,E] int32
    const float* W1 = (const float*)d_in[2];   // [2,16]
    const float* b1 = (const float*)d_in[3];   // [16]
    const float* W2 = (const float*)d_in[4];   // [16,2]
    const float* b2 = (const float*)d_in[5];   // [2]
    float2* out = (float2*)d_out;

    const int* src = ei;
    const int* dst = ei + N_EDGES;
    const float2* x2 = (const float2*)x;

    const int T = 256;
    const int gN = (N_NODES + T - 1) / T;
    const int gE = (N_EDGES + T - 1) / T;

    k_init_deg<<<gN, T>>>();
    k_degree<<<gE, T>>>(dst);
    k_pre1<<<gN, T>>>(x2);
    k_scatter1<<<gE, T>>>(src, dst);
    k_mid<<<gN, T>>>(W1, b1, W2);
    k_scatter2<<<gE, T>>>(src, dst);
    k_out<<<gN, T>>>(b2, out);
}